// round 1
// baseline (speedup 1.0000x reference)
#include <cuda_runtime.h>

#define BATCH 2048
#define INF   512
#define OUTF  512
#define NAG   64

#define TM 64
#define TN 128
#define TK 32

__device__ int g_bucket[BATCH];
__device__ int g_offsets[NAG + 1];

typedef unsigned long long u64;

__device__ __forceinline__ u64 pack2(float a, float b) {
    u64 r; asm("mov.b64 %0, {%1, %2};" : "=l"(r) : "f"(a), "f"(b)); return r;
}
__device__ __forceinline__ void unpack2(u64 v, float& a, float& b) {
    asm("mov.b64 {%0, %1}, %2;" : "=f"(a), "=f"(b) : "l"(v));
}
__device__ __forceinline__ void ffma2(u64& d, u64 a, u64 b) {
    asm("fma.rn.f32x2 %0, %1, %2, %0;" : "+l"(d) : "l"(a), "l"(b));
}

// ---------------------------------------------------------------------------
// Kernel 1: counting sort of batch rows by agent id into g_bucket/g_offsets.
// Order within a bucket is atomics-dependent but the final output is
// order-invariant (each row written exactly once), so graph replays are
// deterministic in the only sense that matters.
// ---------------------------------------------------------------------------
__global__ __launch_bounds__(1024) void bucket_kernel(const int* __restrict__ which) {
    __shared__ int cnt[NAG];
    __shared__ int run[NAG];
    const int t = threadIdx.x;
    if (t < NAG) cnt[t] = 0;
    __syncthreads();
    for (int i = t; i < BATCH; i += blockDim.x)
        atomicAdd(&cnt[which[i]], 1);
    __syncthreads();
    if (t == 0) {
        int s = 0;
        for (int a = 0; a < NAG; a++) { run[a] = s; g_offsets[a] = s; s += cnt[a]; }
        g_offsets[NAG] = s;
    }
    __syncthreads();
    for (int i = t; i < BATCH; i += blockDim.x) {
        const int a = which[i];
        const int p = atomicAdd(&run[a], 1);
        g_bucket[p] = i;
    }
}

// ---------------------------------------------------------------------------
// Kernel 2: per-(agent, n-tile) GEMM over the agent's gathered rows.
// block = (n_tile, agent). 128 threads, thread tile 8m x 8n, m packed in
// f32x2 pairs -> 32 FFMA2 (64 MAC) per k per thread.
// ---------------------------------------------------------------------------
__global__ __launch_bounds__(128) void agent_gemm_kernel(
    const float* __restrict__ x, const float* __restrict__ w,
    const float* __restrict__ bias, float* __restrict__ out)
{
    const int a   = blockIdx.y;
    const int n0  = blockIdx.x * TN;
    const int off = g_offsets[a];
    const int cnt = g_offsets[a + 1] - off;
    if (cnt == 0) return;

    __shared__ float Ws[TK][TN + 4];   // [k][n], stride 132 floats (16B-aligned rows)
    __shared__ float Xs[TK][TM + 4];   // [k][m], stride 68 floats

    const float* Wa = w + (size_t)a * OUTF * INF;
    const int t  = threadIdx.x;
    const int tn = t & 15;   // n-group: outputs tn*8 .. tn*8+7
    const int tm = t >> 4;   // m-group: rows    tm*8 .. tm*8+7
    const int wr = t >> 2;   // W load: row group base (0..31)
    const int wc = t & 3;    // W load: float4 column  (0..3)
    const int xr = t >> 1;   // X load: row (0..63)
    const int xh = t & 1;    // X load: k half

    // bias for this thread's 8 outputs
    float bv[8];
    {
        const float4* bp = (const float4*)(bias + a * OUTF + n0 + tn * 8);
        const float4 b0 = bp[0], b1 = bp[1];
        bv[0]=b0.x; bv[1]=b0.y; bv[2]=b0.z; bv[3]=b0.w;
        bv[4]=b1.x; bv[5]=b1.y; bv[6]=b1.z; bv[7]=b1.w;
    }

    for (int m0 = 0; m0 < cnt; m0 += TM) {
        const int xg = (m0 + xr < cnt) ? g_bucket[off + m0 + xr] : -1;

        u64 acc[4][8];
        #pragma unroll
        for (int i = 0; i < 4; i++)
            #pragma unroll
            for (int j = 0; j < 8; j++) acc[i][j] = 0ull;

        for (int k0 = 0; k0 < INF; k0 += TK) {
            // ---- load W tile [TN rows x TK k], transpose into Ws[k][n] ----
            #pragma unroll
            for (int g = 0; g < 4; g++) {
                const int n = wr + g * 32;
                const float4* src = (const float4*)(Wa + (size_t)(n0 + n) * INF + k0);
                const float4 v0 = src[wc];
                const float4 v1 = src[wc + 4];
                const int kA = wc * 4, kB = (wc + 4) * 4;
                Ws[kA+0][n]=v0.x; Ws[kA+1][n]=v0.y; Ws[kA+2][n]=v0.z; Ws[kA+3][n]=v0.w;
                Ws[kB+0][n]=v1.x; Ws[kB+1][n]=v1.y; Ws[kB+2][n]=v1.z; Ws[kB+3][n]=v1.w;
            }
            // ---- load X tile [TM rows x TK k] (gathered), transpose ----
            if (xg >= 0) {
                const float4* src = (const float4*)(x + (size_t)xg * INF + k0 + xh * 16);
                #pragma unroll
                for (int j2 = 0; j2 < 4; j2++) {
                    const float4 v = src[j2];
                    const int k = xh * 16 + j2 * 4;
                    Xs[k+0][xr]=v.x; Xs[k+1][xr]=v.y; Xs[k+2][xr]=v.z; Xs[k+3][xr]=v.w;
                }
            } else {
                #pragma unroll
                for (int j2 = 0; j2 < 4; j2++) {
                    const int k = xh * 16 + j2 * 4;
                    Xs[k+0][xr]=0.f; Xs[k+1][xr]=0.f; Xs[k+2][xr]=0.f; Xs[k+3][xr]=0.f;
                }
            }
            __syncthreads();

            // ---- compute: 32 FFMA2 per k ----
            #pragma unroll
            for (int k = 0; k < TK; k++) {
                const ulonglong2* xrp = (const ulonglong2*)&Xs[k][tm * 8];
                const ulonglong2 xa = xrp[0], xb = xrp[1];
                const u64 xp[4] = {xa.x, xa.y, xb.x, xb.y};
                const float4 wa4 = *(const float4*)&Ws[k][tn * 8];
                const float4 wb4 = *(const float4*)&Ws[k][tn * 8 + 4];
                const float wv[8] = {wa4.x, wa4.y, wa4.z, wa4.w,
                                     wb4.x, wb4.y, wb4.z, wb4.w};
                #pragma unroll
                for (int j = 0; j < 8; j++) {
                    const u64 wd = pack2(wv[j], wv[j]);
                    #pragma unroll
                    for (int i = 0; i < 4; i++) ffma2(acc[i][j], xp[i], wd);
                }
            }
            __syncthreads();
        }

        // ---- epilogue: unpack, add bias, scatter rows ----
        #pragma unroll
        for (int i = 0; i < 4; i++) {
            float lo[8], hi[8];
            #pragma unroll
            for (int j = 0; j < 8; j++) unpack2(acc[i][j], lo[j], hi[j]);
            const int mA = m0 + tm * 8 + 2 * i;
            if (mA < cnt) {
                const int r = g_bucket[off + mA];
                float4* op = (float4*)(out + (size_t)r * OUTF + n0 + tn * 8);
                op[0] = make_float4(lo[0]+bv[0], lo[1]+bv[1], lo[2]+bv[2], lo[3]+bv[3]);
                op[1] = make_float4(lo[4]+bv[4], lo[5]+bv[5], lo[6]+bv[6], lo[7]+bv[7]);
            }
            if (mA + 1 < cnt) {
                const int r = g_bucket[off + mA + 1];
                float4* op = (float4*)(out + (size_t)r * OUTF + n0 + tn * 8);
                op[0] = make_float4(hi[0]+bv[0], hi[1]+bv[1], hi[2]+bv[2], hi[3]+bv[3]);
                op[1] = make_float4(hi[4]+bv[4], hi[5]+bv[5], hi[6]+bv[6], hi[7]+bv[7]);
            }
        }
    }
}

extern "C" void kernel_launch(void* const* d_in, const int* in_sizes, int n_in,
                              void* d_out, int out_size) {
    const int*   which = (const int*)d_in[0];
    const float* x     = (const float*)d_in[1];
    const float* w     = (const float*)d_in[2];
    const float* b     = (const float*)d_in[3];
    float* out = (float*)d_out;

    bucket_kernel<<<1, 1024>>>(which);
    agent_gemm_kernel<<<dim3(OUTF / TN, NAG), 128>>>(x, w, b, out);
}